// round 4
// baseline (speedup 1.0000x reference)
#include <cuda_runtime.h>
#include <math.h>
#include <stdint.h>

// ---------------------------------------------------------------------------
// Problem dimensions (fixed by the reference)
// ---------------------------------------------------------------------------
#define B_   256
#define T_   256
#define DIN  256
#define H_   1024
#define FC_  512
#define DOUT 24
#define G4   4096   // 4*H

// ---------------------------------------------------------------------------
// Device scratch (static globals — no allocation allowed)
// ---------------------------------------------------------------------------
static __device__ float g_xw[(size_t)T_ * B_ * G4];  // [t][b][4H], b_all baked in (1.07 GB)
static __device__ float g_h[2][(size_t)B_ * H_];     // ping-pong hidden state
static __device__ float g_c[2][(size_t)B_ * H_];     // ping-pong cell state
static __device__ float g_tmp[(size_t)B_ * FC_];     // fc1 activation

// ---------------------------------------------------------------------------
// Packed fp32x2 helpers (Blackwell FFMA2: 2x fp32 FMA throughput)
// ---------------------------------------------------------------------------
__device__ __forceinline__ unsigned long long pk2(float lo, float hi) {
    unsigned long long r;
    asm("mov.b64 %0, {%1, %2};" : "=l"(r) : "f"(lo), "f"(hi));
    return r;
}
__device__ __forceinline__ void fma2(unsigned long long& d,
                                     unsigned long long a,
                                     unsigned long long b) {
    asm("fma.rn.f32x2 %0, %1, %2, %0;" : "+l"(d) : "l"(a), "l"(b));
}
__device__ __forceinline__ float2 upk(unsigned long long v) {
    float2 f;
    asm("mov.b64 {%0, %1}, %2;" : "=f"(f.x), "=f"(f.y) : "l"(v));
    return f;
}
__device__ __forceinline__ float sigm(float x) {
    return 1.0f / (1.0f + expf(-x));
}

// ---------------------------------------------------------------------------
// Kernel 1: xW = x @ Wx + (b_lin + b_extra)
//   GEMM M=65536 (rows ordered [t][b]), N=4096, K=256.
//   128x128 block tile, 256 threads, 8x8 per thread via FFMA2.
// ---------------------------------------------------------------------------
__global__ __launch_bounds__(256) void xw_gemm(
    const float* __restrict__ x,       // [B][T][DIN]
    const float* __restrict__ Wx,      // [DIN][4H]
    const float* __restrict__ b_lin,   // [4H]
    const float* __restrict__ b_extra) // [4H]
{
    __shared__ __align__(16) float sA[16 * 132];  // [k][m], padded stride 132
    __shared__ __align__(16) float sB[16 * 132];  // [k][n], padded stride 132

    const int tid = threadIdx.x;
    const int tm = tid >> 4;        // 0..15, covers 8 m-rows
    const int tn = tid & 15;        // 0..15, covers 8 n-cols
    const int r0 = blockIdx.y * 128;      // output row (t-major) base
    const int n0 = blockIdx.x * 128;      // output col base
    const int t  = r0 >> 8;               // 128 | 256 -> one t per block
    const int b0 = r0 & 255;

    unsigned long long acc[8][4];
#pragma unroll
    for (int i = 0; i < 8; i++)
#pragma unroll
        for (int p = 0; p < 4; p++) acc[i][p] = 0ULL;

    for (int k0 = 0; k0 < DIN; k0 += 16) {
        // --- stage A tile: 128 rows x 16 k -> 512 float4, 2 per thread ---
#pragma unroll
        for (int li = 0; li < 2; li++) {
            int idx = tid + li * 256;
            int r = idx >> 2, q = idx & 3;
            float4 v = *reinterpret_cast<const float4*>(
                &x[((size_t)(b0 + r) * T_ + t) * DIN + k0 + q * 4]);
            sA[(q * 4 + 0) * 132 + r] = v.x;
            sA[(q * 4 + 1) * 132 + r] = v.y;
            sA[(q * 4 + 2) * 132 + r] = v.z;
            sA[(q * 4 + 3) * 132 + r] = v.w;
        }
        // --- stage B tile: 16 k x 128 n -> 512 float4, 2 per thread ---
#pragma unroll
        for (int li = 0; li < 2; li++) {
            int idx = tid + li * 256;
            int k = idx >> 5, q = idx & 31;
            *reinterpret_cast<float4*>(&sB[k * 132 + q * 4]) =
                *reinterpret_cast<const float4*>(
                    &Wx[(size_t)(k0 + k) * G4 + n0 + q * 4]);
        }
        __syncthreads();

#pragma unroll
        for (int k = 0; k < 16; k++) {
            float4 a0 = *reinterpret_cast<const float4*>(&sA[k * 132 + tm * 8]);
            float4 a1 = *reinterpret_cast<const float4*>(&sA[k * 132 + tm * 8 + 4]);
            ulonglong2 bv0 = *reinterpret_cast<const ulonglong2*>(&sB[k * 132 + tn * 8]);
            ulonglong2 bv1 = *reinterpret_cast<const ulonglong2*>(&sB[k * 132 + tn * 8 + 4]);
            unsigned long long bb[4] = {bv0.x, bv0.y, bv1.x, bv1.y};
            unsigned long long pa[8];
            pa[0] = pk2(a0.x, a0.x); pa[1] = pk2(a0.y, a0.y);
            pa[2] = pk2(a0.z, a0.z); pa[3] = pk2(a0.w, a0.w);
            pa[4] = pk2(a1.x, a1.x); pa[5] = pk2(a1.y, a1.y);
            pa[6] = pk2(a1.z, a1.z); pa[7] = pk2(a1.w, a1.w);
#pragma unroll
            for (int i = 0; i < 8; i++) {
                fma2(acc[i][0], pa[i], bb[0]);
                fma2(acc[i][1], pa[i], bb[1]);
                fma2(acc[i][2], pa[i], bb[2]);
                fma2(acc[i][3], pa[i], bb[3]);
            }
        }
        __syncthreads();
    }

    // --- epilogue: add biases, write xW ---
#pragma unroll
    for (int i = 0; i < 8; i++) {
        int row = r0 + tm * 8 + i;
        float* orow = &g_xw[(size_t)row * G4 + n0 + tn * 8];
#pragma unroll
        for (int p = 0; p < 4; p++) {
            float2 v = upk(acc[i][p]);
            int c0 = n0 + tn * 8 + 2 * p;
            orow[2 * p]     = v.x + b_lin[c0]     + b_extra[c0];
            orow[2 * p + 1] = v.y + b_lin[c0 + 1] + b_extra[c0 + 1];
        }
    }
}

// ---------------------------------------------------------------------------
// Kernel 2: one TLSTM step (fused h@Ux for 4 gates + c@Wd + nonlinearities)
//   Block tile: 64 batch rows x 32 hidden cols -> 5 fused [64x32] GEMMs, K=1024.
//   Grid: (1024/32, 256/64) = (32, 4) = 128 blocks.
// ---------------------------------------------------------------------------
__global__ __launch_bounds__(256) void step_kernel(
    int t,
    const float* __restrict__ Ux,        // [H][4H]
    const float* __restrict__ Wd,        // [H][H]
    const float* __restrict__ bd,        // [H]
    const float* __restrict__ b_decomp,  // [H]
    const float* __restrict__ elapsed)   // [B][T]
{
    __shared__ __align__(16) float smem[10240];  // 40 KB, two overlaid layouts
    float* sAh = smem;            // [16][68]
    float* sAc = smem + 1088;     // [16][68]
    float* sB  = smem + 2176;     // [16][160]: cols 0..127 = 4 gates x 32, 128..159 = Wd
    float* sGate = smem;          // epilogue overlay: [64][128]
    float* sCst  = smem + 8192;   // epilogue overlay: [64][32]

    const int pr = t & 1;
    const float* h_in = g_h[pr];
    const float* c_in = g_c[pr];
    float* h_out = g_h[1 - pr];
    float* c_out = g_c[1 - pr];
    const bool zi = (t == 0);  // h0 = c0 = 0

    const int tid = threadIdx.x;
    const int tm = tid >> 4;   // 0..15 -> 4 batch rows each
    const int tn = tid & 15;   // 0..15 -> 8 gate-cols + 2 Wd-cols each
    const int n0 = blockIdx.x * 32;
    const int b0 = blockIdx.y * 64;

    unsigned long long accg[4][4];
    unsigned long long accd[4];
#pragma unroll
    for (int i = 0; i < 4; i++) {
        accd[i] = 0ULL;
#pragma unroll
        for (int p = 0; p < 4; p++) accg[i][p] = 0ULL;
    }

    for (int k0 = 0; k0 < H_; k0 += 16) {
        // --- stage A tiles (h and c): 64 rows x 16 k each, 1 float4/thread ---
        {
            int r = tid >> 2, q = tid & 3;
            float4 vh, vc;
            if (zi) {
                vh = make_float4(0.f, 0.f, 0.f, 0.f);
                vc = vh;
            } else {
                vh = *reinterpret_cast<const float4*>(
                    &h_in[(size_t)(b0 + r) * H_ + k0 + q * 4]);
                vc = *reinterpret_cast<const float4*>(
                    &c_in[(size_t)(b0 + r) * H_ + k0 + q * 4]);
            }
            sAh[(q * 4 + 0) * 68 + r] = vh.x;
            sAh[(q * 4 + 1) * 68 + r] = vh.y;
            sAh[(q * 4 + 2) * 68 + r] = vh.z;
            sAh[(q * 4 + 3) * 68 + r] = vh.w;
            sAc[(q * 4 + 0) * 68 + r] = vc.x;
            sAc[(q * 4 + 1) * 68 + r] = vc.y;
            sAc[(q * 4 + 2) * 68 + r] = vc.z;
            sAc[(q * 4 + 3) * 68 + r] = vc.w;
        }
        // --- stage B tile: 640 float4 (512 Ux across 4 gates + 128 Wd) ---
        for (int idx = tid; idx < 640; idx += 256) {
            if (idx < 512) {
                int k = idx >> 5, rem = idx & 31;
                int ga = rem >> 3, q = rem & 7;
                *reinterpret_cast<float4*>(&sB[k * 160 + ga * 32 + q * 4]) =
                    *reinterpret_cast<const float4*>(
                        &Ux[(size_t)(k0 + k) * G4 + ga * H_ + n0 + q * 4]);
            } else {
                int j = idx - 512;
                int k = j >> 3, q = j & 7;
                *reinterpret_cast<float4*>(&sB[k * 160 + 128 + q * 4]) =
                    *reinterpret_cast<const float4*>(
                        &Wd[(size_t)(k0 + k) * H_ + n0 + q * 4]);
            }
        }
        __syncthreads();

#pragma unroll
        for (int k = 0; k < 16; k++) {
            float4 ah = *reinterpret_cast<const float4*>(&sAh[k * 68 + tm * 4]);
            float4 ac = *reinterpret_cast<const float4*>(&sAc[k * 68 + tm * 4]);
            ulonglong2 bg0 = *reinterpret_cast<const ulonglong2*>(&sB[k * 160 + tn * 8]);
            ulonglong2 bg1 = *reinterpret_cast<const ulonglong2*>(&sB[k * 160 + tn * 8 + 4]);
            unsigned long long bdv =
                *reinterpret_cast<const unsigned long long*>(&sB[k * 160 + 128 + tn * 2]);
            unsigned long long bb[4] = {bg0.x, bg0.y, bg1.x, bg1.y};
            unsigned long long ph[4], pc[4];
            ph[0] = pk2(ah.x, ah.x); ph[1] = pk2(ah.y, ah.y);
            ph[2] = pk2(ah.z, ah.z); ph[3] = pk2(ah.w, ah.w);
            pc[0] = pk2(ac.x, ac.x); pc[1] = pk2(ac.y, ac.y);
            pc[2] = pk2(ac.z, ac.z); pc[3] = pk2(ac.w, ac.w);
#pragma unroll
            for (int i = 0; i < 4; i++) {
                fma2(accg[i][0], ph[i], bb[0]);
                fma2(accg[i][1], ph[i], bb[1]);
                fma2(accg[i][2], ph[i], bb[2]);
                fma2(accg[i][3], ph[i], bb[3]);
                fma2(accd[i],    pc[i], bdv);
            }
        }
        __syncthreads();
    }

    // --- epilogue: gate exchange through smem ---
#pragma unroll
    for (int i = 0; i < 4; i++) {
        int m = tm * 4 + i;
#pragma unroll
        for (int p = 0; p < 4; p++) {
            float2 v = upk(accg[i][p]);
            sGate[m * 128 + tn * 8 + 2 * p]     = v.x;
            sGate[m * 128 + tn * 8 + 2 * p + 1] = v.y;
        }
        float2 vd = upk(accd[i]);
        sCst[m * 32 + tn * 2]     = vd.x;
        sCst[m * 32 + tn * 2 + 1] = vd.y;
    }
    __syncthreads();

    // --- finalize: time-decay decomposition + LSTM gate math ---
    for (int e = tid; e < 64 * 32; e += 256) {
        int m = e >> 5, jn = e & 31;
        int b = b0 + m, n = n0 + jn;

        float cst = tanhf(sCst[m * 32 + jn] + bd[n] + b_decomp[n]);
        float cp = zi ? 0.0f : c_in[(size_t)b * H_ + n];
        float dt = elapsed[(size_t)b * T_ + t];
        float Td = 1.0f / logf(dt + 2.7183f);
        float cmid = cp - cst + Td * cst;

        const float* xr = &g_xw[((size_t)t * B_ + b) * G4];  // includes b_lin+b_extra
        float gi = sGate[m * 128 +  0 + jn] + xr[0 * H_ + n];
        float gf = sGate[m * 128 + 32 + jn] + xr[1 * H_ + n];
        float go = sGate[m * 128 + 64 + jn] + xr[2 * H_ + n];
        float gc = sGate[m * 128 + 96 + jn] + xr[3 * H_ + n];

        float cn = sigm(gf) * cmid + sigm(gi) * tanhf(gc);
        float hn = sigm(go) * tanhf(cn);
        c_out[(size_t)b * H_ + n] = cn;
        h_out[(size_t)b * H_ + n] = hn;
    }
}

// ---------------------------------------------------------------------------
// Kernel 3: tmp = relu(h_T @ fc1_w + fc1_b)   (h_T lives in g_h[0])
// ---------------------------------------------------------------------------
__global__ __launch_bounds__(256) void fc1_kernel(
    const float* __restrict__ w,     // [H][FC]
    const float* __restrict__ bias)  // [FC]
{
    int idx = blockIdx.x * 256 + threadIdx.x;  // B*FC = 131072
    int b = idx >> 9, n = idx & 511;
    const float* hrow = &g_h[0][(size_t)b * H_];
    float acc = bias[n];
#pragma unroll 8
    for (int k = 0; k < H_; k++)
        acc += hrow[k] * w[(size_t)k * FC_ + n];
    g_tmp[idx] = fmaxf(acc, 0.0f);
}

// ---------------------------------------------------------------------------
// Kernel 4: out = tmp @ fco_w + fco_b
// ---------------------------------------------------------------------------
__global__ __launch_bounds__(256) void fco_kernel(
    const float* __restrict__ w,      // [FC][DOUT]
    const float* __restrict__ bias,   // [DOUT]
    float* __restrict__ out)          // [B][DOUT]
{
    int idx = blockIdx.x * 256 + threadIdx.x;  // B*DOUT = 6144
    if (idx >= B_ * DOUT) return;
    int b = idx / DOUT, n = idx % DOUT;
    const float* trow = &g_tmp[(size_t)b * FC_];
    float acc = bias[n];
#pragma unroll 8
    for (int k = 0; k < FC_; k++)
        acc += trow[k] * w[(size_t)k * DOUT + n];
    out[idx] = acc;
}

// ---------------------------------------------------------------------------
// Launch
// ---------------------------------------------------------------------------
extern "C" void kernel_launch(void* const* d_in, const int* in_sizes, int n_in,
                              void* d_out, int out_size) {
    (void)in_sizes; (void)n_in; (void)out_size;
    const float* x        = (const float*)d_in[0];
    const float* elapsed  = (const float*)d_in[1];
    const float* Wx       = (const float*)d_in[2];
    const float* Ux       = (const float*)d_in[3];
    const float* b_lin    = (const float*)d_in[4];
    const float* b_extra  = (const float*)d_in[5];
    const float* Wd       = (const float*)d_in[6];
    const float* bd       = (const float*)d_in[7];
    const float* b_decomp = (const float*)d_in[8];
    const float* fc1_w    = (const float*)d_in[9];
    const float* fc1_b    = (const float*)d_in[10];
    const float* fco_w    = (const float*)d_in[11];
    const float* fco_b    = (const float*)d_in[12];
    float* out = (float*)d_out;

    // 1) Fused input projection for all timesteps (biases baked in).
    xw_gemm<<<dim3(G4 / 128, (T_ * B_) / 128), 256>>>(x, Wx, b_lin, b_extra);

    // 2) Sequential recurrence: one launch per step (kernel boundary = grid sync).
    for (int t = 0; t < T_; t++)
        step_kernel<<<dim3(H_ / 32, B_ / 64), 256>>>(t, Ux, Wd, bd, b_decomp, elapsed);

    // 3) Output head on the final hidden state (in g_h[0] after t=255).
    fc1_kernel<<<(B_ * FC_) / 256, 256>>>(fc1_w, fc1_b);
    fco_kernel<<<(B_ * DOUT + 255) / 256, 256>>>(fco_w, fco_b, out);
}